// round 2
// baseline (speedup 1.0000x reference)
#include <cuda_runtime.h>
#include <math.h>

#define IMG_H 1088
#define IMG_W 1920
#define BATCH 8
#define TILE  32
#define NT    256

#define W_IMG 48   // padded width of img tile (floats)
#define W_STD 40   // padded width of all other stage tiles (floats)

// Fused Canny pipeline, 32x32 output tile per CTA, 1x4 quad register blocking.
// smem layout (floats), with aliasing of dead regions:
//   [0    .. 2112)  s_img  44x48   -> reused as s_gx 36x40 after stage 1a
//   [2112 .. 3872)  s_tmp  44x40   -> reused as s_gy 36x40 after stage 1b
//   [3872 .. 5392)  s_blur 38x40
//   [5392 .. 6832)  s_mag  36x40
//   [6832 .. 8192)  s_thin 34x40
__global__ __launch_bounds__(NT) void canny_kernel(
    const float* __restrict__ img,
    const float* __restrict__ gk,
    float* __restrict__ out,
    long long N)
{
    __shared__ __align__(16) float sbuf[8192];
    __shared__ float s_r[7], s_c[7];
    float* s_img  = sbuf;
    float* s_tmp  = sbuf + 2112;
    float* s_blur = sbuf + 3872;
    float* s_mag  = sbuf + 5392;
    float* s_thin = sbuf + 6832;
    float* s_gx   = sbuf;          // aliases s_img (dead after stage 1a)
    float* s_gy   = sbuf + 2112;   // aliases s_tmp (dead after stage 1b)

    const int tid = threadIdx.x;
    const int bx = blockIdx.x * TILE;
    const int by = blockIdx.y * TILE;
    const int b  = blockIdx.z;
    const float* ip = img + (long long)b * (IMG_H * IMG_W);

    if (tid < 7) {
        // gaussian is a normalized outer product: k[i][j] = k[i][4]*k[4][j]/k[4][4]
        float s = sqrtf(gk[4 * 7 + 4]);
        s_r[tid] = gk[tid * 7 + 4] / s;   // vertical factor
        s_c[tid] = gk[4 * 7 + tid] / s;   // horizontal factor
    }

    // ---- stage 0: load img tile 44x44 (zero padded outside image) ----
    for (int idx = tid; idx < 44 * 44; idx += NT) {
        int r = idx / 44, c = idx - r * 44;
        int gy = by - 6 + r, gx = bx - 6 + c;
        float v = 0.0f;
        if ((unsigned)gy < IMG_H && (unsigned)gx < IMG_W)
            v = ip[(long long)gy * IMG_W + gx];
        s_img[r * W_IMG + c] = v;
    }
    __syncthreads();

    const float c0 = s_c[0], c1 = s_c[1], c2 = s_c[2], c3 = s_c[3],
                c4 = s_c[4], c5 = s_c[5], c6 = s_c[6];
    const float r0 = s_r[0], r1 = s_r[1], r2 = s_r[2], r3 = s_r[3],
                r4 = s_r[4], r5 = s_r[5], r6 = s_r[6];

    // ---- stage 1a: horizontal 7-tap, 44 rows x 10 quads (40 cols, 38 valid) ----
    for (int idx = tid; idx < 44 * 10; idx += NT) {
        int r = idx / 10, q = idx - r * 10;
        const float4* row = (const float4*)(s_img + r * W_IMG);
        float4 A = row[q], B = row[q + 1], C = row[q + 2];
        float w0 = A.x, w1 = A.y, w2 = A.z, w3 = A.w;
        float w4 = B.x, w5 = B.y, w6 = B.z, w7 = B.w;
        float w8 = C.x, w9 = C.y;
        float o0 = c0*w0 + c1*w1 + c2*w2 + c3*w3 + c4*w4 + c5*w5 + c6*w6;
        float o1 = c0*w1 + c1*w2 + c2*w3 + c3*w4 + c4*w5 + c5*w6 + c6*w7;
        float o2 = c0*w2 + c1*w3 + c2*w4 + c3*w5 + c4*w6 + c5*w7 + c6*w8;
        float o3 = c0*w3 + c1*w4 + c2*w5 + c3*w6 + c4*w7 + c5*w8 + c6*w9;
        ((float4*)(s_tmp + r * W_STD))[q] = make_float4(o0, o1, o2, o3);
    }
    __syncthreads();

    // ---- stage 1b: vertical 7-tap -> blurred 38 rows x 10 quads, zero outside ----
    for (int idx = tid; idx < 38 * 10; idx += NT) {
        int r = idx / 10, q = idx - r * 10;
        const float* base = s_tmp + r * W_STD + 4 * q;
        float4 t0 = *(const float4*)(base);
        float4 t1 = *(const float4*)(base + 1 * W_STD);
        float4 t2 = *(const float4*)(base + 2 * W_STD);
        float4 t3 = *(const float4*)(base + 3 * W_STD);
        float4 t4 = *(const float4*)(base + 4 * W_STD);
        float4 t5 = *(const float4*)(base + 5 * W_STD);
        float4 t6 = *(const float4*)(base + 6 * W_STD);
        float ax = r0*t0.x + r1*t1.x + r2*t2.x + r3*t3.x + r4*t4.x + r5*t5.x + r6*t6.x;
        float ay = r0*t0.y + r1*t1.y + r2*t2.y + r3*t3.y + r4*t4.y + r5*t5.y + r6*t6.y;
        float az = r0*t0.z + r1*t1.z + r2*t2.z + r3*t3.z + r4*t4.z + r5*t5.z + r6*t6.z;
        float aw = r0*t0.w + r1*t1.w + r2*t2.w + r3*t3.w + r4*t4.w + r5*t5.w + r6*t6.w;
        int gy = by - 3 + r;
        bool rok = (unsigned)gy < IMG_H;
        int gx0 = bx - 3 + 4 * q;
        float4 o;
        o.x = (rok && (unsigned)(gx0    ) < IMG_W) ? ax : 0.0f;
        o.y = (rok && (unsigned)(gx0 + 1) < IMG_W) ? ay : 0.0f;
        o.z = (rok && (unsigned)(gx0 + 2) < IMG_W) ? az : 0.0f;
        o.w = (rok && (unsigned)(gx0 + 3) < IMG_W) ? aw : 0.0f;
        ((float4*)(s_blur + r * W_STD))[q] = o;
    }
    __syncthreads();

    // ---- stage 2: sobel -> mag (masked), gx, gy cached; 36 rows x 9 quads ----
    for (int idx = tid; idx < 36 * 9; idx += NT) {
        int r = idx / 9, q = idx - r * 9;
        const float* base = s_blur + r * W_STD + 4 * q;
        float4 a0 = *(const float4*)(base);
        float4 a1 = *(const float4*)(base + 4);
        float4 b0 = *(const float4*)(base + W_STD);
        float4 b1 = *(const float4*)(base + W_STD + 4);
        float4 d0 = *(const float4*)(base + 2 * W_STD);
        float4 d1 = *(const float4*)(base + 2 * W_STD + 4);
        float t[3][8] = {
            {a0.x, a0.y, a0.z, a0.w, a1.x, a1.y, a1.z, a1.w},
            {b0.x, b0.y, b0.z, b0.w, b1.x, b1.y, b1.z, b1.w},
            {d0.x, d0.y, d0.z, d0.w, d1.x, d1.y, d1.z, d1.w}};
        int gy = by - 2 + r;
        bool rok = (unsigned)gy < IMG_H;
        int gx0 = bx - 2 + 4 * q;
        float4 om, ogx, ogy;
        float* pm = (float*)&om; float* pgx = (float*)&ogx; float* pgy = (float*)&ogy;
        #pragma unroll
        for (int j = 0; j < 4; j++) {
            float b00 = t[0][j], b01 = t[0][j+1], b02 = t[0][j+2];
            float b10 = t[1][j],                  b12 = t[1][j+2];
            float b20 = t[2][j], b21 = t[2][j+1], b22 = t[2][j+2];
            float gxv = b00 - b02 + 2.0f*b10 - 2.0f*b12 + b20 - b22;
            float gyv = b00 + 2.0f*b01 + b02 - b20 - 2.0f*b21 - b22;
            float m = sqrtf(gxv * gxv + gyv * gyv);
            bool ok = rok && (unsigned)(gx0 + j) < IMG_W;
            pm[j]  = ok ? m : 0.0f;
            pgx[j] = gxv;
            pgy[j] = gyv;
        }
        ((float4*)(s_mag + r * W_STD))[q] = om;
        ((float4*)(s_gx  + r * W_STD))[q] = ogx;
        ((float4*)(s_gy  + r * W_STD))[q] = ogy;
    }
    __syncthreads();

    // ---- stage 3: non-max suppression -> thin, 34 rows x 9 quads ----
    for (int idx = tid; idx < 34 * 9; idx += NT) {
        int r = idx / 9, q = idx - r * 9;
        const float* base = s_mag + r * W_STD + 4 * q;
        float4 a0 = *(const float4*)(base);
        float4 a1 = *(const float4*)(base + 4);
        float4 b0 = *(const float4*)(base + W_STD);
        float4 b1 = *(const float4*)(base + W_STD + 4);
        float4 d0 = *(const float4*)(base + 2 * W_STD);
        float4 d1 = *(const float4*)(base + 2 * W_STD + 4);
        float t[3][8] = {
            {a0.x, a0.y, a0.z, a0.w, a1.x, a1.y, a1.z, a1.w},
            {b0.x, b0.y, b0.z, b0.w, b1.x, b1.y, b1.z, b1.w},
            {d0.x, d0.y, d0.z, d0.w, d1.x, d1.y, d1.z, d1.w}};
        int gy = by - 1 + r;
        bool rok = (unsigned)gy < IMG_H;
        int gx0 = bx - 1 + 4 * q;
        float4 o; float* po = (float*)&o;
        #pragma unroll
        for (int j = 0; j < 4; j++) {
            float m00 = t[0][j], m01 = t[0][j+1], m02 = t[0][j+2];
            float m10 = t[1][j],                  m12 = t[1][j+2];
            float m20 = t[2][j], m21 = t[2][j+1], m22 = t[2][j+2];
            float m   = t[1][j+1];
            float sx = m00 - m02 + 2.0f * m10 - 2.0f * m12 + m20 - m22;
            float sy = m00 + 2.0f * m01 + m02 - m20 - 2.0f * m21 - m22;
            float v = (m >= sx && m >= sy) ? m : 0.0f;
            bool ok = rok && (unsigned)(gx0 + j) < IMG_W;
            po[j] = ok ? v : 0.0f;
        }
        ((float4*)(s_thin + r * W_STD))[q] = o;
    }
    __syncthreads();

    // ---- stage 4: hysteresis + 5 plane writes, 1 quad per thread ----
    {
        int ly = tid >> 3;
        int q  = tid & 7;
        int lx = 4 * q;

        // blurred at output quad: blur origin (-3,-3) -> row ly+3, cols lx+3..lx+6
        const float* bb = s_blur + (ly + 3) * W_STD + lx;
        float4 B0 = *(const float4*)(bb);
        float4 B1 = *(const float4*)(bb + 4);
        float blv[4] = {B0.w, B1.x, B1.y, B1.z};

        // mag / gx / gy at row ly+2, cols lx+2..lx+5 (origin (-2,-2))
        const float* mb = s_mag + (ly + 2) * W_STD + lx;
        float4 M0 = *(const float4*)(mb);
        float4 M1 = *(const float4*)(mb + 4);
        float mv[4] = {M0.z, M0.w, M1.x, M1.y};
        const float* gxb = s_gx + (ly + 2) * W_STD + lx;
        float4 GX0 = *(const float4*)(gxb);
        float4 GX1 = *(const float4*)(gxb + 4);
        float gxv[4] = {GX0.z, GX0.w, GX1.x, GX1.y};
        const float* gyb = s_gy + (ly + 2) * W_STD + lx;
        float4 GY0 = *(const float4*)(gyb);
        float4 GY1 = *(const float4*)(gyb + 4);
        float gyv[4] = {GY0.z, GY0.w, GY1.x, GY1.y};

        // thin window rows ly..ly+2, cols lx..lx+7 (origin (-1,-1))
        const float* tb = s_thin + ly * W_STD + lx;
        float4 T00 = *(const float4*)(tb);
        float4 T01 = *(const float4*)(tb + 4);
        float4 T10 = *(const float4*)(tb + W_STD);
        float4 T11 = *(const float4*)(tb + W_STD + 4);
        float4 T20 = *(const float4*)(tb + 2 * W_STD);
        float4 T21 = *(const float4*)(tb + 2 * W_STD + 4);
        float tw[3][8] = {
            {T00.x, T00.y, T00.z, T00.w, T01.x, T01.y, T01.z, T01.w},
            {T10.x, T10.y, T10.z, T10.w, T11.x, T11.y, T11.z, T11.w},
            {T20.x, T20.y, T20.z, T20.w, T21.x, T21.y, T21.z, T21.w}};

        float4 oB, oM, oO, oT, oE;
        float* pB = (float*)&oB; float* pM = (float*)&oM; float* pO = (float*)&oO;
        float* pT = (float*)&oT; float* pE = (float*)&oE;
        #pragma unroll
        for (int j = 0; j < 4; j++) {
            float tcen = tw[1][j + 1];
            bool strong = tcen > 3.0f;
            bool weak   = (tcen > 1.0f) && (tcen <= 3.0f);
            int nsum =
                (tw[0][j] > 3.0f) + (tw[0][j+1] > 3.0f) + (tw[0][j+2] > 3.0f) +
                (tw[1][j] > 3.0f) +                       (tw[1][j+2] > 3.0f) +
                (tw[2][j] > 3.0f) + (tw[2][j+1] > 3.0f) + (tw[2][j+2] > 3.0f);
            bool sn   = (nsum - 8 * (strong ? 1 : 0)) > 0;
            bool edge = strong || (weak && sn);
            pB[j] = blv[j];
            pM[j] = mv[j];
            pO[j] = atan2f(gyv[j], gxv[j]);
            pT[j] = tcen;
            pE[j] = edge ? 1.0f : 0.0f;
        }

        long long o = (long long)b * (IMG_H * IMG_W)
                    + (long long)(by + ly) * IMG_W + (bx + lx);
        *(float4*)(out + o)         = oB;
        *(float4*)(out + N + o)     = oM;
        *(float4*)(out + 2 * N + o) = oO;
        *(float4*)(out + 3 * N + o) = oT;
        *(float4*)(out + 4 * N + o) = oE;
    }
}

extern "C" void kernel_launch(void* const* d_in, const int* in_sizes, int n_in,
                              void* d_out, int out_size) {
    const float* img = (const float*)d_in[0];
    const float* gk  = (const float*)d_in[1];
    float* out = (float*)d_out;
    long long N = (long long)out_size / 5;   // 5 concatenated planes
    dim3 grid(IMG_W / TILE, IMG_H / TILE, BATCH);
    canny_kernel<<<grid, NT>>>(img, gk, out, N);
}

// round 3
// speedup vs baseline: 1.7244x; 1.7244x over previous
#include <cuda_runtime.h>
#include <math.h>

#define IMG_H 1088
#define IMG_W 1920
#define BATCH 8
#define TILE  32
#define NT    256

// padded widths (odd -> conflict-free stride-1 lane access)
#define WI 45   // s_img rows of 44
#define WT 39   // s_tmp / s_blur
#define WM 37   // s_mag / s_gx / s_gy
#define WN 35   // s_thin

// smem float offsets (aliasing dead regions):
//   s_img  44x45 = 1980   -> aliased by s_gx (36x37=1332) after stage 1a
//   s_tmp  44x39 = 1716   -> aliased by s_gy (36x37=1332) after stage 1b
//   s_blur 38x39 = 1482
//   s_mag  36x37 = 1332
//   s_thin 34x35 = 1190
#define OFF_IMG  0
#define OFF_TMP  1980
#define OFF_BLUR 3696
#define OFF_MAG  5178
#define OFF_THIN 6510
#define SM_FLOATS 7700

__global__ __launch_bounds__(NT) void canny_kernel(
    const float* __restrict__ img,
    const float* __restrict__ gk,
    float* __restrict__ out,
    long long N)
{
    __shared__ float sbuf[SM_FLOATS];
    __shared__ float s_r[7], s_c[7];
    float* s_img  = sbuf + OFF_IMG;
    float* s_tmp  = sbuf + OFF_TMP;
    float* s_blur = sbuf + OFF_BLUR;
    float* s_mag  = sbuf + OFF_MAG;
    float* s_thin = sbuf + OFF_THIN;
    float* s_gx   = sbuf + OFF_IMG;   // alias: img dead after stage 1a
    float* s_gy   = sbuf + OFF_TMP;   // alias: tmp dead after stage 1b

    const int tid = threadIdx.x;
    const int bx = blockIdx.x * TILE;
    const int by = blockIdx.y * TILE;
    const int b  = blockIdx.z;
    const float* ip = img + (long long)b * (IMG_H * IMG_W);

    if (tid < 7) {
        // gaussian is a normalized outer product: k[i][j] = k[i][4]*k[4][j]/k[4][4]
        float s = sqrtf(gk[4 * 7 + 4]);
        s_r[tid] = gk[tid * 7 + 4] / s;   // vertical factor
        s_c[tid] = gk[4 * 7 + tid] / s;   // horizontal factor
    }

    // ---- stage 0: load img tile 44x44, zero padded outside image ----
    for (int idx = tid; idx < 44 * 44; idx += NT) {
        int r = idx / 44, c = idx - r * 44;
        int gy = by - 6 + r, gx = bx - 6 + c;
        float v = 0.0f;
        if ((unsigned)gy < IMG_H && (unsigned)gx < IMG_W)
            v = ip[(long long)gy * IMG_W + gx];
        s_img[r * WI + c] = v;
    }
    __syncthreads();

    const float c0 = s_c[0], c1 = s_c[1], c2 = s_c[2], c3 = s_c[3],
                c4 = s_c[4], c5 = s_c[5], c6 = s_c[6];
    const float r0 = s_r[0], r1 = s_r[1], r2 = s_r[2], r3 = s_r[3],
                r4 = s_r[4], r5 = s_r[5], r6 = s_r[6];

    // ---- stage 1a: horizontal 7-tap, 44 rows x 38 cols, per-point ----
    for (int idx = tid; idx < 44 * 38; idx += NT) {
        int r = idx / 38, c = idx - r * 38;
        const float* p = s_img + r * WI + c;
        s_tmp[r * WT + c] = c0*p[0] + c1*p[1] + c2*p[2] + c3*p[3]
                          + c4*p[4] + c5*p[5] + c6*p[6];
    }
    __syncthreads();

    // ---- stage 1b: vertical 7-tap -> blur 38x38, 4-row blocks, zero outside ----
    // tasks: 38 cols x 10 row-blocks
    for (int idx = tid; idx < 38 * 10; idx += NT) {
        int c = idx % 38, rb = idx / 38;
        int rr = rb * 4;
        float tv[10];
        #pragma unroll
        for (int i = 0; i < 10; i++)
            tv[i] = (rr + i < 44) ? s_tmp[(rr + i) * WT + c] : 0.0f;
        int gx = bx - 3 + c;
        bool cok = (unsigned)gx < IMG_W;
        #pragma unroll
        for (int i = 0; i < 4; i++) {
            int r = rr + i;
            if (r < 38) {
                float v = r0*tv[i] + r1*tv[i+1] + r2*tv[i+2] + r3*tv[i+3]
                        + r4*tv[i+4] + r5*tv[i+5] + r6*tv[i+6];
                int gy = by - 3 + r;
                bool ok = cok && (unsigned)gy < IMG_H;
                s_blur[r * WT + c] = ok ? v : 0.0f;
            }
        }
    }
    __syncthreads();

    // ---- stage 2: sobel -> mag (masked) + gx,gy cached; 36x36, 4-row blocks ----
    // tasks: 36 cols x 9 row-blocks (exact)
    for (int idx = tid; idx < 36 * 9; idx += NT) {
        int c = idx % 36, rb = idx / 36;
        int rr = rb * 4;
        float p[6], q[6];   // p = colL - colR ; q = colL + 2*colM + colR
        #pragma unroll
        for (int i = 0; i < 6; i++) {
            const float* row = s_blur + (rr + i) * WT + c;
            float a = row[0], m = row[1], d = row[2];
            p[i] = a - d;
            q[i] = a + 2.0f * m + d;
        }
        int gxp = bx - 2 + c;
        bool cok = (unsigned)gxp < IMG_W;
        #pragma unroll
        for (int i = 0; i < 4; i++) {
            int r = rr + i;
            float gxv = p[i] + 2.0f * p[i+1] + p[i+2];
            float gyv = q[i] - q[i+2];
            float m = sqrtf(gxv * gxv + gyv * gyv);
            int gy = by - 2 + r;
            bool ok = cok && (unsigned)gy < IMG_H;
            s_mag[r * WM + c] = ok ? m : 0.0f;
            s_gx [r * WM + c] = gxv;
            s_gy [r * WM + c] = gyv;
        }
    }
    __syncthreads();

    // ---- stage 3: non-max suppression -> thin 34x34, 4-row blocks ----
    // tasks: 34 cols x 9 row-blocks (last block: 2 rows)
    for (int idx = tid; idx < 34 * 9; idx += NT) {
        int c = idx % 34, rb = idx / 34;
        int rr = rb * 4;
        float p[6], q[6], mm[6];
        #pragma unroll
        for (int i = 0; i < 6; i++) {
            float a = 0.0f, m = 0.0f, d = 0.0f;
            if (rr + i < 36) {
                const float* row = s_mag + (rr + i) * WM + c;
                a = row[0]; m = row[1]; d = row[2];
            }
            p[i] = a - d;
            q[i] = a + 2.0f * m + d;
            mm[i] = m;
        }
        int gxp = bx - 1 + c;
        bool cok = (unsigned)gxp < IMG_W;
        #pragma unroll
        for (int i = 0; i < 4; i++) {
            int r = rr + i;
            if (r < 34) {
                float sx = p[i] + 2.0f * p[i+1] + p[i+2];
                float sy = q[i] - q[i+2];
                float m  = mm[i+1];
                float v = (m >= sx && m >= sy) ? m : 0.0f;
                int gy = by - 1 + r;
                bool ok = cok && (unsigned)gy < IMG_H;
                s_thin[r * WN + c] = ok ? v : 0.0f;
            }
        }
    }
    __syncthreads();

    // ---- stage 4: hysteresis + 5 plane writes; 1 task/thread, 4-row column ----
    {
        int c  = tid & 31;        // output column
        int rb = tid >> 5;        // row block (0..7)
        int rr = rb * 4;

        // strong flags over thin window rows rr..rr+5, cols c..c+2
        // column partial sums: cc[i][k] = sum of (thin>3) over rows rr+i..rr+i+2, col c+k
        int sb[6][3];
        #pragma unroll
        for (int i = 0; i < 6; i++) {
            const float* row = s_thin + (rr + i) * WN + c;
            sb[i][0] = row[0] > 3.0f;
            sb[i][1] = row[1] > 3.0f;
            sb[i][2] = row[2] > 3.0f;
        }

        long long obase = (long long)b * (IMG_H * IMG_W)
                        + (long long)(by + rr) * IMG_W + (bx + c);
        #pragma unroll
        for (int i = 0; i < 4; i++) {
            float blv = s_blur[(rr + i + 3) * WT + (c + 3)];
            float mv  = s_mag [(rr + i + 2) * WM + (c + 2)];
            float gxv = s_gx  [(rr + i + 2) * WM + (c + 2)];
            float gyv = s_gy  [(rr + i + 2) * WM + (c + 2)];
            float tc  = s_thin[(rr + i + 1) * WN + (c + 1)];

            bool strong = tc > 3.0f;
            bool weak   = (tc > 1.0f) && (tc <= 3.0f);
            int full9 = sb[i][0] + sb[i][1] + sb[i][2]
                      + sb[i+1][0] + sb[i+1][1] + sb[i+1][2]
                      + sb[i+2][0] + sb[i+2][1] + sb[i+2][2];
            // conv with hyst_k (center -8) > 0  <=>  full9 - 9*center_strong > 0
            bool sn   = (full9 - 9 * sb[i+1][1]) > 0;
            bool edge = strong || (weak && sn);

            long long o = obase + (long long)i * IMG_W;
            out[o]         = blv;
            out[N + o]     = mv;
            out[2 * N + o] = atan2f(gyv, gxv);
            out[3 * N + o] = tc;
            out[4 * N + o] = edge ? 1.0f : 0.0f;
        }
    }
}

extern "C" void kernel_launch(void* const* d_in, const int* in_sizes, int n_in,
                              void* d_out, int out_size) {
    const float* img = (const float*)d_in[0];
    const float* gk  = (const float*)d_in[1];
    float* out = (float*)d_out;
    long long N = (long long)out_size / 5;   // 5 concatenated planes
    dim3 grid(IMG_W / TILE, IMG_H / TILE, BATCH);
    canny_kernel<<<grid, NT>>>(img, gk, out, N);
}